// round 10
// baseline (speedup 1.0000x reference)
#include <cuda_runtime.h>
#include <math.h>
#include <stdint.h>

// ProteinFeatures: kNN graph -> 446-dim edge features -> MLP(446->446 gelu -> 128)
// Round 1: correct fp32 baseline. GEMMs use packed fma.rn.f32x2 (Blackwell FFMA2).

constexpr int cB    = 2;
constexpr int cN    = 4096;
constexpr int cA    = 5;
constexpr int cK    = 30;    // TOPK
constexpr int cEIN  = 446;
constexpr int cEPAD = 448;
constexpr int cEOUT = 128;
constexpr int cM    = cB * cN * cK;   // 245760 edge rows

// ---------------- scratch (device globals; no allocation allowed) ----------------
__device__ float g_lf[cB * cN * 9];
__device__ int   g_eidx[cM];
__device__ float g_matt[cM];
__device__ float g_E[(size_t)cM * cEPAD];     // ~440 MB
__device__ float g_H[(size_t)cM * cEPAD];     // ~440 MB
__device__ float g_W1p[cEPAD * cEPAD];
__device__ float g_b1p[cEPAD];
__device__ float g_W2p[cEPAD * cEOUT];

// ---------------- helpers ----------------
__device__ __forceinline__ void norm3(float& x, float& y, float& z){
    float n = sqrtf(x*x + y*y + z*z);
    float inv = 1.f / fmaxf(n, 1e-12f);
    x *= inv; y *= inv; z *= inv;
}
__device__ __forceinline__ float sgnf(float a){ return (a > 0.f) ? 1.f : ((a < 0.f) ? -1.f : 0.f); }

__device__ __forceinline__ unsigned long long pack2(float lo, float hi){
    unsigned long long r;
    asm("mov.b64 %0, {%1, %2};" : "=l"(r) : "f"(lo), "f"(hi));
    return r;
}
__device__ __forceinline__ void unpack2(unsigned long long v, float& lo, float& hi){
    asm("mov.b64 {%0, %1}, %2;" : "=f"(lo), "=f"(hi) : "l"(v));
}
__device__ __forceinline__ void fma2(unsigned long long& d, unsigned long long a, unsigned long long b){
    asm("fma.rn.f32x2 %0, %1, %2, %0;" : "+l"(d) : "l"(a), "l"(b));
}

// ---------------- 1. pad weights into 448-aligned buffers ----------------
__global__ void pad_weights_kernel(const float* __restrict__ W1, const float* __restrict__ b1,
                                   const float* __restrict__ W2){
    int idx = blockIdx.x * blockDim.x + threadIdx.x;
    if (idx < cEPAD * cEPAD){
        int r = idx / cEPAD, c = idx - r * cEPAD;
        g_W1p[idx] = (r < cEIN && c < cEIN) ? W1[r * cEIN + c] : 0.f;
    }
    if (idx < cEPAD * cEOUT){
        int r = idx / cEOUT, c = idx - r * cEOUT;
        g_W2p[idx] = (r < cEIN) ? W2[r * cEOUT + c] : 0.f;
    }
    if (idx < cEPAD) g_b1p[idx] = (idx < cEIN) ? b1[idx] : 0.f;
}

// ---------------- 2. local frames lf = [b_, n_, b_ x n_] ----------------
__global__ void frames_kernel(const float* __restrict__ X){
    int idx = blockIdx.x * blockDim.x + threadIdx.x;
    if (idx >= cB * cN) return;
    int b = idx / cN, i = idx - b * cN;
    const float* Xb = X + (size_t)b * cN * cA * 3;
    float cx = Xb[(i*cA+1)*3+0], cy = Xb[(i*cA+1)*3+1], cz = Xb[(i*cA+1)*3+2];
    float ux, uy, uz;
    if (i == 0){ ux = uy = uz = 1.f; }
    else {
        ux = cx - Xb[((i-1)*cA+1)*3+0];
        uy = cy - Xb[((i-1)*cA+1)*3+1];
        uz = cz - Xb[((i-1)*cA+1)*3+2];
    }
    norm3(ux, uy, uz);
    float bx, by, bz, nx, ny, nz;
    if (i == cN - 1){
        bx = by = bz = 1.f; norm3(bx, by, bz);
        nx = ny = nz = 1.f; norm3(nx, ny, nz);
    } else {
        float vx = Xb[((i+1)*cA+1)*3+0] - cx;
        float vy = Xb[((i+1)*cA+1)*3+1] - cy;
        float vz = Xb[((i+1)*cA+1)*3+2] - cz;
        norm3(vx, vy, vz);                       // u[i+1]
        bx = ux - vx; by = uy - vy; bz = uz - vz;
        norm3(bx, by, bz);
        nx = uy*vz - uz*vy; ny = uz*vx - ux*vz; nz = ux*vy - uy*vx;
        norm3(nx, ny, nz);
    }
    float ccx = by*nz - bz*ny, ccy = bz*nx - bx*nz, ccz = bx*ny - by*nx;  // not normalized
    float* o = g_lf + (size_t)idx * 9;
    o[0]=bx; o[1]=by; o[2]=bz; o[3]=nx; o[4]=ny; o[5]=nz; o[6]=ccx; o[7]=ccy; o[8]=ccz;
}

// ---------------- 3. top-k (30 smallest D_adj, ties -> lower index) ----------------
__global__ void __launch_bounds__(256) topk_kernel(const float* __restrict__ X,
                                                   const float* __restrict__ mask){
    __shared__ float sD[cN];
    __shared__ float sred[8];
    __shared__ unsigned long long skey[8];
    int bi = blockIdx.x;
    int b = bi / cN, i = bi - b * cN;
    const float* Xb = X + (size_t)b * cN * cA * 3;
    const float* mb = mask + b * cN;
    float cax = Xb[(i*cA+1)*3+0], cay = Xb[(i*cA+1)*3+1], caz = Xb[(i*cA+1)*3+2];
    float mi = mb[i];
    int tid = threadIdx.x, lane = tid & 31, wid = tid >> 5;

    float lmax = 0.f;
    for (int j = tid; j < cN; j += 256){
        float dx = Xb[(j*cA+1)*3+0] - cax;
        float dy = Xb[(j*cA+1)*3+1] - cay;
        float dz = Xb[(j*cA+1)*3+2] - caz;
        float m2 = mi * mb[j];
        float D  = m2 * sqrtf(dx*dx + dy*dy + dz*dz + 1e-6f);
        sD[j] = D;
        lmax = fmaxf(lmax, D);
    }
    #pragma unroll
    for (int off = 16; off; off >>= 1) lmax = fmaxf(lmax, __shfl_xor_sync(0xffffffffu, lmax, off));
    if (lane == 0) sred[wid] = lmax;
    __syncthreads();
    if (tid == 0){
        float m = sred[0];
        #pragma unroll
        for (int w = 1; w < 8; w++) m = fmaxf(m, sred[w]);
        sred[0] = m;
    }
    __syncthreads();
    float rowmax = sred[0];
    for (int j = tid; j < cN; j += 256){
        float m2 = mi * mb[j];
        sD[j] += (1.f - m2) * rowmax;           // D_adj
    }
    __syncthreads();

    for (int k = 0; k < cK; k++){
        unsigned long long best = ~0ULL;
        for (int j = tid; j < cN; j += 256){
            unsigned long long key = ((unsigned long long)__float_as_uint(sD[j]) << 32) | (unsigned)j;
            if (key < best) best = key;
        }
        #pragma unroll
        for (int off = 16; off; off >>= 1){
            unsigned long long o = __shfl_xor_sync(0xffffffffu, best, off);
            if (o < best) best = o;
        }
        if (lane == 0) skey[wid] = best;
        __syncthreads();
        if (tid == 0){
            unsigned long long bb = skey[0];
            #pragma unroll
            for (int w = 1; w < 8; w++) if (skey[w] < bb) bb = skey[w];
            int j = (int)(bb & 0xffffffffULL);
            g_eidx[bi * cK + k] = j;
            g_matt[bi * cK + k] = mi * mb[j];
            sD[j] = __int_as_float(0x7f800000);  // +inf
        }
        __syncthreads();
    }
}

// ---------------- 4. build edge feature rows (one warp per edge) ----------------
__global__ void __launch_bounds__(128) build_e_kernel(
    const float* __restrict__ X, const float* __restrict__ mask_atoms,
    const float* __restrict__ means, const float* __restrict__ stds,
    const float* __restrict__ mul_w, const float* __restrict__ bias_w,
    const float* __restrict__ aa_pair_embed, const float* __restrict__ relpos_embed,
    const float* __restrict__ mask_embed, const int* __restrict__ aa,
    const int* __restrict__ residx, const int* __restrict__ chains)
{
    __shared__ float sXG[4][25];
    int w = threadIdx.x >> 5, lane = threadIdx.x & 31;
    int e = blockIdx.x * 4 + w;
    int b = e / (cN * cK);
    int rem = e - b * (cN * cK);
    int i = rem / cK;
    int j = g_eidx[e];
    float ma = g_matt[e];
    float* __restrict__ Erow = g_E + (size_t)e * cEPAD;
    const float* Xi = X + ((size_t)(b*cN + i) * cA) * 3;
    const float* Xj = X + ((size_t)(b*cN + j) * cA) * 3;

    // --- atom-pair xg (25 pairs, index = a_nb*5 + a_self) ---
    if (lane < 25){
        int pnb = lane / 5, qsf = lane - pnb * 5;
        float dx = Xj[pnb*3+0] - Xi[qsf*3+0];
        float dy = Xj[pnb*3+1] - Xi[qsf*3+1];
        float dz = Xj[pnb*3+2] - Xi[qsf*3+2];
        float Dab = sqrtf(dx*dx + dy*dy + dz*dz + 1e-12f);
        float xg = mul_w[lane] * Dab + bias_w[lane];
        float mp = mask_atoms[(size_t)(b*cN + j)*cA + pnb];
        float mq = mask_atoms[(size_t)(b*cN + j)*cA + qsf];
        sXG[w][lane] = xg * (mp * mq);
    }
    __syncwarp();

    // --- 400 RBF features: E[16 + pr*16 + kr] ---
    {
        int kr = lane & 15;
        float mean = means[kr];
        float sd = fabsf(stds[kr]) + 0.01f;
        float inv = 1.f / sd;
        float coef = 0.3989422804014327f * inv * ma;
        int base = lane >> 4;
        #pragma unroll
        for (int t = 0; t < 13; t++){
            int pr = base + 2 * t;
            if (pr < 25){
                float z = (sXG[w][pr] - mean) * inv;
                Erow[16 + pr*16 + kr] = __expf(-0.5f * z * z) * coef;
            }
        }
    }

    // --- E_pos (no mask) + aa-pair (masked) ---
    if (lane < 16){
        int ri = residx[b*cN + i], rj = residx[b*cN + j];
        int d = ri - rj + 32;
        d = d < 0 ? 0 : (d > 64 ? 64 : d);
        int ceq = (chains[b*cN + i] == chains[b*cN + j]) ? 1 : 0;
        Erow[lane] = relpos_embed[d*16 + lane] + mask_embed[ceq*16 + lane];
        int ap = aa[b*cN + i] * 22 + aa[b*cN + j];
        Erow[430 + lane] = aa_pair_embed[ap*16 + lane] * ma;
    }
    if (lane < 2) Erow[446 + lane] = 0.f;   // pad columns

    // --- O_feat: t(3), q(4), 1-2|t|(3), 1-2|q|(4) at offset 416 ---
    {
        const float* lfi = g_lf + (size_t)(b*cN + i) * 9;
        const float* lfj = g_lf + (size_t)(b*cN + j) * 9;
        float L[9], Lj[9];
        #pragma unroll
        for (int s = 0; s < 9; s++){ L[s] = lfi[s]; Lj[s] = lfj[s]; }
        float dx = Xj[3+0] - Xi[3+0];
        float dy = Xj[3+1] - Xi[3+1];
        float dz = Xj[3+2] - Xi[3+2];
        float t0 = L[0]*dx + L[1]*dy + L[2]*dz;
        float t1 = L[3]*dx + L[4]*dy + L[5]*dz;
        float t2 = L[6]*dx + L[7]*dy + L[8]*dz;
        float tn = sqrtf(t0*t0 + t1*t1 + t2*t2);
        float ts = ma / fmaxf(tn, 1e-12f);
        t0 *= ts; t1 *= ts; t2 *= ts;
        // r[i][l] = sum_j lf_i[j][i] * lf_j[j][l]
        float r00 = L[0]*Lj[0] + L[3]*Lj[3] + L[6]*Lj[6];
        float r01 = L[0]*Lj[1] + L[3]*Lj[4] + L[6]*Lj[7];
        float r02 = L[0]*Lj[2] + L[3]*Lj[5] + L[6]*Lj[8];
        float r10 = L[1]*Lj[0] + L[4]*Lj[3] + L[7]*Lj[6];
        float r11 = L[1]*Lj[1] + L[4]*Lj[4] + L[7]*Lj[7];
        float r12 = L[1]*Lj[2] + L[4]*Lj[5] + L[7]*Lj[8];
        float r20 = L[2]*Lj[0] + L[5]*Lj[3] + L[8]*Lj[6];
        float r21 = L[2]*Lj[1] + L[5]*Lj[4] + L[8]*Lj[7];
        float r22 = L[2]*Lj[2] + L[5]*Lj[5] + L[8]*Lj[8];
        float qx = sgnf(r21 - r12) * 0.5f * sqrtf(fabsf(1.f + r00 - r11 - r22) + 1e-12f);
        float qy = sgnf(r02 - r20) * 0.5f * sqrtf(fabsf(1.f - r00 + r11 - r22) + 1e-12f);
        float qz = sgnf(r10 - r01) * 0.5f * sqrtf(fabsf(1.f - r00 - r11 + r22) + 1e-12f);
        float tr = 1.f + r00 + r11 + r22;
        float qw = 0.5f * sqrtf((tr > 0.f ? tr : 0.f) + 1e-12f);
        float qn = sqrtf(qx*qx + qy*qy + qz*qz + qw*qw);
        float qs = ma / fmaxf(qn, 1e-12f);
        qx *= qs; qy *= qs; qz *= qs; qw *= qs;
        if (lane < 14){
            float v = 0.f;
            switch (lane){
                case 0:  v = t0; break;
                case 1:  v = t1; break;
                case 2:  v = t2; break;
                case 3:  v = qx; break;
                case 4:  v = qy; break;
                case 5:  v = qz; break;
                case 6:  v = qw; break;
                case 7:  v = 1.f - 2.f*fabsf(t0); break;
                case 8:  v = 1.f - 2.f*fabsf(t1); break;
                case 9:  v = 1.f - 2.f*fabsf(t2); break;
                case 10: v = 1.f - 2.f*fabsf(qx); break;
                case 11: v = 1.f - 2.f*fabsf(qy); break;
                case 12: v = 1.f - 2.f*fabsf(qz); break;
                case 13: v = 1.f - 2.f*fabsf(qw); break;
            }
            Erow[416 + lane] = v;
        }
    }
}

// ---------------- 5. fp32 GEMM (f32x2 packed FMA), 128x64x16 tiles ----------------
template<bool GELU>
__global__ void __launch_bounds__(256) gemm_kernel(
    const float* __restrict__ Am, const float* __restrict__ Bm,
    const float* __restrict__ bias, float* __restrict__ Cm,
    int Ndim, int Kdim)
{
    __shared__ float As[16][132];
    __shared__ float Bs[16][72];
    int tid = threadIdx.x;
    int m0 = blockIdx.y * 128;
    int n0 = blockIdx.x * 64;
    int lr  = tid >> 2;              // 0..63  (A tile row)
    int lc  = (tid & 3) * 4;         // 0,4,8,12 (A tile k-offset)
    int bkr = tid >> 4;              // 0..15  (B tile k-row)
    int bc  = (tid & 15) * 4;        // 0..60  (B tile col)
    int ty  = tid >> 3;              // 0..31  -> 4 rows each
    int tx  = tid & 7;               // 0..7   -> 8 cols each
    unsigned long long acc[4][4] = {};
    const float* Ap = Am + (size_t)m0 * Kdim;

    for (int k0 = 0; k0 < Kdim; k0 += 16){
        float4 a0 = *(const float4*)(Ap + (size_t)lr * Kdim + k0 + lc);
        float4 a1 = *(const float4*)(Ap + (size_t)(lr + 64) * Kdim + k0 + lc);
        float4 bv = *(const float4*)(Bm + (size_t)(k0 + bkr) * Ndim + n0 + bc);
        __syncthreads();
        As[lc+0][lr] = a0.x; As[lc+1][lr] = a0.y; As[lc+2][lr] = a0.z; As[lc+3][lr] = a0.w;
        As[lc+0][lr+64] = a1.x; As[lc+1][lr+64] = a1.y; As[lc+2][lr+64] = a1.z; As[lc+3][lr+64] = a1.w;
        *(float4*)&Bs[bkr][bc] = bv;
        __syncthreads();
        #pragma unroll
        for (int kk = 0; kk < 16; kk++){
            float4 av = *(const float4*)&As[kk][ty*4];
            ulonglong2 b01 = *(const ulonglong2*)&Bs[kk][tx*8];
            ulonglong2 b23 = *(const ulonglong2*)&Bs[kk][tx*8 + 4];
            unsigned long long ad;
            ad = pack2(av.x, av.x);
            fma2(acc[0][0], ad, b01.x); fma2(acc[0][1], ad, b01.y);
            fma2(acc[0][2], ad, b23.x); fma2(acc[0][3], ad, b23.y);
            ad = pack2(av.y, av.y);
            fma2(acc[1][0], ad, b01.x); fma2(acc[1][1], ad, b01.y);
            fma2(acc[1][2], ad, b23.x); fma2(acc[1][3], ad, b23.y);
            ad = pack2(av.z, av.z);
            fma2(acc[2][0], ad, b01.x); fma2(acc[2][1], ad, b01.y);
            fma2(acc[2][2], ad, b23.x); fma2(acc[2][3], ad, b23.y);
            ad = pack2(av.w, av.w);
            fma2(acc[3][0], ad, b01.x); fma2(acc[3][1], ad, b01.y);
            fma2(acc[3][2], ad, b23.x); fma2(acc[3][3], ad, b23.y);
        }
    }

    #pragma unroll
    for (int r = 0; r < 4; r++){
        float cv[8];
        unpack2(acc[r][0], cv[0], cv[1]);
        unpack2(acc[r][1], cv[2], cv[3]);
        unpack2(acc[r][2], cv[4], cv[5]);
        unpack2(acc[r][3], cv[6], cv[7]);
        size_t row = (size_t)m0 + ty*4 + r;
        int nc = n0 + tx*8;
        #pragma unroll
        for (int c = 0; c < 8; c++){
            float v = cv[c] + bias[nc + c];
            if (GELU) v = 0.5f * v * (1.f + erff(v * 0.70710678118654752f));
            cv[c] = v;
        }
        float4* dst = (float4*)(Cm + row * (size_t)Ndim + nc);
        dst[0] = make_float4(cv[0], cv[1], cv[2], cv[3]);
        dst[1] = make_float4(cv[4], cv[5], cv[6], cv[7]);
    }
}

// ---------------- launch ----------------
extern "C" void kernel_launch(void* const* d_in, const int* in_sizes, int n_in,
                              void* d_out, int out_size){
    const float* X          = (const float*)d_in[0];
    const float* mask       = (const float*)d_in[1];
    const float* mask_atoms = (const float*)d_in[2];
    const float* means      = (const float*)d_in[3];
    const float* stds       = (const float*)d_in[4];
    const float* mul_w      = (const float*)d_in[5];
    const float* bias_w     = (const float*)d_in[6];
    const float* aa_pair    = (const float*)d_in[7];
    const float* relpos     = (const float*)d_in[8];
    const float* mask_emb   = (const float*)d_in[9];
    const float* W1         = (const float*)d_in[10];
    const float* b1         = (const float*)d_in[11];
    const float* W2         = (const float*)d_in[12];
    const float* b2         = (const float*)d_in[13];
    const int*   aa         = (const int*)d_in[14];
    const int*   residx     = (const int*)d_in[15];
    const int*   chains     = (const int*)d_in[16];
    float* out = (float*)d_out;

    float *pE, *pH, *pW1p, *pb1p, *pW2p;
    cudaGetSymbolAddress((void**)&pE,   g_E);
    cudaGetSymbolAddress((void**)&pH,   g_H);
    cudaGetSymbolAddress((void**)&pW1p, g_W1p);
    cudaGetSymbolAddress((void**)&pb1p, g_b1p);
    cudaGetSymbolAddress((void**)&pW2p, g_W2p);

    pad_weights_kernel<<<(cEPAD*cEPAD + 255)/256, 256>>>(W1, b1, W2);
    frames_kernel<<<(cB*cN + 127)/128, 128>>>(X);
    topk_kernel<<<cB*cN, 256>>>(X, mask);
    build_e_kernel<<<cM/4, 128>>>(X, mask_atoms, means, stds, mul_w, bias_w,
                                  aa_pair, relpos, mask_emb, aa, residx, chains);
    gemm_kernel<true ><<<dim3(cEPAD/64, cM/128), 256>>>(pE, pW1p, pb1p, pH, cEPAD, cEPAD);
    gemm_kernel<false><<<dim3(cEOUT/64, cM/128), 256>>>(pH, pW2p, b2, out, cEOUT, cEPAD);
}

// round 11
// speedup vs baseline: 1.6397x; 1.6397x over previous
#include <cuda_runtime.h>
#include <math.h>
#include <stdint.h>

// ProteinFeatures: kNN graph -> 446-dim edge features -> MLP(446->446 gelu -> 128)
// Round 1: correct fp32 baseline. GEMMs use packed fma.rn.f32x2 (Blackwell FFMA2).

constexpr int cB    = 2;
constexpr int cN    = 4096;
constexpr int cA    = 5;
constexpr int cK    = 30;    // TOPK
constexpr int cEIN  = 446;
constexpr int cEPAD = 448;
constexpr int cEOUT = 128;
constexpr int cM    = cB * cN * cK;   // 245760 edge rows

// ---------------- scratch (device globals; no allocation allowed) ----------------
__device__ float g_lf[cB * cN * 9];
__device__ int   g_eidx[cM];
__device__ float g_matt[cM];
__device__ float g_E[(size_t)cM * cEPAD];     // ~440 MB
__device__ float g_H[(size_t)cM * cEPAD];     // ~440 MB
__device__ float g_W1p[cEPAD * cEPAD];
__device__ float g_b1p[cEPAD];
__device__ float g_W2p[cEPAD * cEOUT];

// ---------------- helpers ----------------
__device__ __forceinline__ void norm3(float& x, float& y, float& z){
    float n = sqrtf(x*x + y*y + z*z);
    float inv = 1.f / fmaxf(n, 1e-12f);
    x *= inv; y *= inv; z *= inv;
}
__device__ __forceinline__ float sgnf(float a){ return (a > 0.f) ? 1.f : ((a < 0.f) ? -1.f : 0.f); }

__device__ __forceinline__ unsigned long long pack2(float lo, float hi){
    unsigned long long r;
    asm("mov.b64 %0, {%1, %2};" : "=l"(r) : "f"(lo), "f"(hi));
    return r;
}
__device__ __forceinline__ void unpack2(unsigned long long v, float& lo, float& hi){
    asm("mov.b64 {%0, %1}, %2;" : "=f"(lo), "=f"(hi) : "l"(v));
}
__device__ __forceinline__ void fma2(unsigned long long& d, unsigned long long a, unsigned long long b){
    asm("fma.rn.f32x2 %0, %1, %2, %0;" : "+l"(d) : "l"(a), "l"(b));
}

// ---------------- 1. pad weights into 448-aligned buffers ----------------
__global__ void pad_weights_kernel(const float* __restrict__ W1, const float* __restrict__ b1,
                                   const float* __restrict__ W2){
    int idx = blockIdx.x * blockDim.x + threadIdx.x;
    if (idx < cEPAD * cEPAD){
        int r = idx / cEPAD, c = idx - r * cEPAD;
        g_W1p[idx] = (r < cEIN && c < cEIN) ? W1[r * cEIN + c] : 0.f;
    }
    if (idx < cEPAD * cEOUT){
        int r = idx / cEOUT, c = idx - r * cEOUT;
        g_W2p[idx] = (r < cEIN) ? W2[r * cEOUT + c] : 0.f;
    }
    if (idx < cEPAD) g_b1p[idx] = (idx < cEIN) ? b1[idx] : 0.f;
}

// ---------------- 2. local frames lf = [b_, n_, b_ x n_] ----------------
__global__ void frames_kernel(const float* __restrict__ X){
    int idx = blockIdx.x * blockDim.x + threadIdx.x;
    if (idx >= cB * cN) return;
    int b = idx / cN, i = idx - b * cN;
    const float* Xb = X + (size_t)b * cN * cA * 3;
    float cx = Xb[(i*cA+1)*3+0], cy = Xb[(i*cA+1)*3+1], cz = Xb[(i*cA+1)*3+2];
    float ux, uy, uz;
    if (i == 0){ ux = uy = uz = 1.f; }
    else {
        ux = cx - Xb[((i-1)*cA+1)*3+0];
        uy = cy - Xb[((i-1)*cA+1)*3+1];
        uz = cz - Xb[((i-1)*cA+1)*3+2];
    }
    norm3(ux, uy, uz);
    float bx, by, bz, nx, ny, nz;
    if (i == cN - 1){
        bx = by = bz = 1.f; norm3(bx, by, bz);
        nx = ny = nz = 1.f; norm3(nx, ny, nz);
    } else {
        float vx = Xb[((i+1)*cA+1)*3+0] - cx;
        float vy = Xb[((i+1)*cA+1)*3+1] - cy;
        float vz = Xb[((i+1)*cA+1)*3+2] - cz;
        norm3(vx, vy, vz);                       // u[i+1]
        bx = ux - vx; by = uy - vy; bz = uz - vz;
        norm3(bx, by, bz);
        nx = uy*vz - uz*vy; ny = uz*vx - ux*vz; nz = ux*vy - uy*vx;
        norm3(nx, ny, nz);
    }
    float ccx = by*nz - bz*ny, ccy = bz*nx - bx*nz, ccz = bx*ny - by*nx;  // not normalized
    float* o = g_lf + (size_t)idx * 9;
    o[0]=bx; o[1]=by; o[2]=bz; o[3]=nx; o[4]=ny; o[5]=nz; o[6]=ccx; o[7]=ccy; o[8]=ccz;
}

// ---------------- 3. top-k (30 smallest D_adj, ties -> lower index) ----------------
__global__ void __launch_bounds__(256) topk_kernel(const float* __restrict__ X,
                                                   const float* __restrict__ mask){
    __shared__ float sD[cN];
    __shared__ float sred[8];
    __shared__ unsigned long long skey[8];
    int bi = blockIdx.x;
    int b = bi / cN, i = bi - b * cN;
    const float* Xb = X + (size_t)b * cN * cA * 3;
    const float* mb = mask + b * cN;
    float cax = Xb[(i*cA+1)*3+0], cay = Xb[(i*cA+1)*3+1], caz = Xb[(i*cA+1)*3+2];
    float mi = mb[i];
    int tid = threadIdx.x, lane = tid & 31, wid = tid >> 5;

    float lmax = 0.f;
    for (int j = tid; j < cN; j += 256){
        float dx = Xb[(j*cA+1)*3+0] - cax;
        float dy = Xb[(j*cA+1)*3+1] - cay;
        float dz = Xb[(j*cA+1)*3+2] - caz;
        float m2 = mi * mb[j];
        float D  = m2 * sqrtf(dx*dx + dy*dy + dz*dz + 1e-6f);
        sD[j] = D;
        lmax = fmaxf(lmax, D);
    }
    #pragma unroll
    for (int off = 16; off; off >>= 1) lmax = fmaxf(lmax, __shfl_xor_sync(0xffffffffu, lmax, off));
    if (lane == 0) sred[wid] = lmax;
    __syncthreads();
    if (tid == 0){
        float m = sred[0];
        #pragma unroll
        for (int w = 1; w < 8; w++) m = fmaxf(m, sred[w]);
        sred[0] = m;
    }
    __syncthreads();
    float rowmax = sred[0];
    for (int j = tid; j < cN; j += 256){
        float m2 = mi * mb[j];
        sD[j] += (1.f - m2) * rowmax;           // D_adj
    }
    __syncthreads();

    for (int k = 0; k < cK; k++){
        unsigned long long best = ~0ULL;
        for (int j = tid; j < cN; j += 256){
            unsigned long long key = ((unsigned long long)__float_as_uint(sD[j]) << 32) | (unsigned)j;
            if (key < best) best = key;
        }
        #pragma unroll
        for (int off = 16; off; off >>= 1){
            unsigned long long o = __shfl_xor_sync(0xffffffffu, best, off);
            if (o < best) best = o;
        }
        if (lane == 0) skey[wid] = best;
        __syncthreads();
        if (tid == 0){
            unsigned long long bb = skey[0];
            #pragma unroll
            for (int w = 1; w < 8; w++) if (skey[w] < bb) bb = skey[w];
            int j = (int)(bb & 0xffffffffULL);
            g_eidx[bi * cK + k] = j;
            g_matt[bi * cK + k] = mi * mb[j];
            sD[j] = __int_as_float(0x7f800000);  // +inf
        }
        __syncthreads();
    }
}

// ---------------- 4. build edge feature rows (one warp per edge) ----------------
__global__ void __launch_bounds__(128) build_e_kernel(
    const float* __restrict__ X, const float* __restrict__ mask_atoms,
    const float* __restrict__ means, const float* __restrict__ stds,
    const float* __restrict__ mul_w, const float* __restrict__ bias_w,
    const float* __restrict__ aa_pair_embed, const float* __restrict__ relpos_embed,
    const float* __restrict__ mask_embed, const int* __restrict__ aa,
    const int* __restrict__ residx, const int* __restrict__ chains)
{
    __shared__ float sXG[4][25];
    int w = threadIdx.x >> 5, lane = threadIdx.x & 31;
    int e = blockIdx.x * 4 + w;
    int b = e / (cN * cK);
    int rem = e - b * (cN * cK);
    int i = rem / cK;
    int j = g_eidx[e];
    float ma = g_matt[e];
    float* __restrict__ Erow = g_E + (size_t)e * cEPAD;
    const float* Xi = X + ((size_t)(b*cN + i) * cA) * 3;
    const float* Xj = X + ((size_t)(b*cN + j) * cA) * 3;

    // --- atom-pair xg (25 pairs, index = a_nb*5 + a_self) ---
    if (lane < 25){
        int pnb = lane / 5, qsf = lane - pnb * 5;
        float dx = Xj[pnb*3+0] - Xi[qsf*3+0];
        float dy = Xj[pnb*3+1] - Xi[qsf*3+1];
        float dz = Xj[pnb*3+2] - Xi[qsf*3+2];
        float Dab = sqrtf(dx*dx + dy*dy + dz*dz + 1e-12f);
        float xg = mul_w[lane] * Dab + bias_w[lane];
        float mp = mask_atoms[(size_t)(b*cN + j)*cA + pnb];
        float mq = mask_atoms[(size_t)(b*cN + j)*cA + qsf];
        sXG[w][lane] = xg * (mp * mq);
    }
    __syncwarp();

    // --- 400 RBF features: E[16 + pr*16 + kr] ---
    {
        int kr = lane & 15;
        float mean = means[kr];
        float sd = fabsf(stds[kr]) + 0.01f;
        float inv = 1.f / sd;
        float coef = 0.3989422804014327f * inv * ma;
        int base = lane >> 4;
        #pragma unroll
        for (int t = 0; t < 13; t++){
            int pr = base + 2 * t;
            if (pr < 25){
                float z = (sXG[w][pr] - mean) * inv;
                Erow[16 + pr*16 + kr] = __expf(-0.5f * z * z) * coef;
            }
        }
    }

    // --- E_pos (no mask) + aa-pair (masked) ---
    if (lane < 16){
        int ri = residx[b*cN + i], rj = residx[b*cN + j];
        int d = ri - rj + 32;
        d = d < 0 ? 0 : (d > 64 ? 64 : d);
        int ceq = (chains[b*cN + i] == chains[b*cN + j]) ? 1 : 0;
        Erow[lane] = relpos_embed[d*16 + lane] + mask_embed[ceq*16 + lane];
        int ap = aa[b*cN + i] * 22 + aa[b*cN + j];
        Erow[430 + lane] = aa_pair_embed[ap*16 + lane] * ma;
    }
    if (lane < 2) Erow[446 + lane] = 0.f;   // pad columns

    // --- O_feat: t(3), q(4), 1-2|t|(3), 1-2|q|(4) at offset 416 ---
    {
        const float* lfi = g_lf + (size_t)(b*cN + i) * 9;
        const float* lfj = g_lf + (size_t)(b*cN + j) * 9;
        float L[9], Lj[9];
        #pragma unroll
        for (int s = 0; s < 9; s++){ L[s] = lfi[s]; Lj[s] = lfj[s]; }
        float dx = Xj[3+0] - Xi[3+0];
        float dy = Xj[3+1] - Xi[3+1];
        float dz = Xj[3+2] - Xi[3+2];
        float t0 = L[0]*dx + L[1]*dy + L[2]*dz;
        float t1 = L[3]*dx + L[4]*dy + L[5]*dz;
        float t2 = L[6]*dx + L[7]*dy + L[8]*dz;
        float tn = sqrtf(t0*t0 + t1*t1 + t2*t2);
        float ts = ma / fmaxf(tn, 1e-12f);
        t0 *= ts; t1 *= ts; t2 *= ts;
        // r[i][l] = sum_j lf_i[j][i] * lf_j[j][l]
        float r00 = L[0]*Lj[0] + L[3]*Lj[3] + L[6]*Lj[6];
        float r01 = L[0]*Lj[1] + L[3]*Lj[4] + L[6]*Lj[7];
        float r02 = L[0]*Lj[2] + L[3]*Lj[5] + L[6]*Lj[8];
        float r10 = L[1]*Lj[0] + L[4]*Lj[3] + L[7]*Lj[6];
        float r11 = L[1]*Lj[1] + L[4]*Lj[4] + L[7]*Lj[7];
        float r12 = L[1]*Lj[2] + L[4]*Lj[5] + L[7]*Lj[8];
        float r20 = L[2]*Lj[0] + L[5]*Lj[3] + L[8]*Lj[6];
        float r21 = L[2]*Lj[1] + L[5]*Lj[4] + L[8]*Lj[7];
        float r22 = L[2]*Lj[2] + L[5]*Lj[5] + L[8]*Lj[8];
        float qx = sgnf(r21 - r12) * 0.5f * sqrtf(fabsf(1.f + r00 - r11 - r22) + 1e-12f);
        float qy = sgnf(r02 - r20) * 0.5f * sqrtf(fabsf(1.f - r00 + r11 - r22) + 1e-12f);
        float qz = sgnf(r10 - r01) * 0.5f * sqrtf(fabsf(1.f - r00 - r11 + r22) + 1e-12f);
        float tr = 1.f + r00 + r11 + r22;
        float qw = 0.5f * sqrtf((tr > 0.f ? tr : 0.f) + 1e-12f);
        float qn = sqrtf(qx*qx + qy*qy + qz*qz + qw*qw);
        float qs = ma / fmaxf(qn, 1e-12f);
        qx *= qs; qy *= qs; qz *= qs; qw *= qs;
        if (lane < 14){
            float v = 0.f;
            switch (lane){
                case 0:  v = t0; break;
                case 1:  v = t1; break;
                case 2:  v = t2; break;
                case 3:  v = qx; break;
                case 4:  v = qy; break;
                case 5:  v = qz; break;
                case 6:  v = qw; break;
                case 7:  v = 1.f - 2.f*fabsf(t0); break;
                case 8:  v = 1.f - 2.f*fabsf(t1); break;
                case 9:  v = 1.f - 2.f*fabsf(t2); break;
                case 10: v = 1.f - 2.f*fabsf(qx); break;
                case 11: v = 1.f - 2.f*fabsf(qy); break;
                case 12: v = 1.f - 2.f*fabsf(qz); break;
                case 13: v = 1.f - 2.f*fabsf(qw); break;
            }
            Erow[416 + lane] = v;
        }
    }
}

// ---------------- 5. fp32 GEMM (f32x2 packed FMA), 128x64x16 tiles ----------------
template<bool GELU>
__global__ void __launch_bounds__(256) gemm_kernel(
    const float* __restrict__ Am, const float* __restrict__ Bm,
    const float* __restrict__ bias, float* __restrict__ Cm,
    int Ndim, int Kdim)
{
    __shared__ float As[16][132];
    __shared__ float Bs[16][72];
    int tid = threadIdx.x;
    int m0 = blockIdx.y * 128;
    int n0 = blockIdx.x * 64;
    int lr  = tid >> 2;              // 0..63  (A tile row)
    int lc  = (tid & 3) * 4;         // 0,4,8,12 (A tile k-offset)
    int bkr = tid >> 4;              // 0..15  (B tile k-row)
    int bc  = (tid & 15) * 4;        // 0..60  (B tile col)
    int ty  = tid >> 3;              // 0..31  -> 4 rows each
    int tx  = tid & 7;               // 0..7   -> 8 cols each
    unsigned long long acc[4][4] = {};
    const float* Ap = Am + (size_t)m0 * Kdim;

    for (int k0 = 0; k0 < Kdim; k0 += 16){
        float4 a0 = *(const float4*)(Ap + (size_t)lr * Kdim + k0 + lc);
        float4 a1 = *(const float4*)(Ap + (size_t)(lr + 64) * Kdim + k0 + lc);
        float4 bv = *(const float4*)(Bm + (size_t)(k0 + bkr) * Ndim + n0 + bc);
        __syncthreads();
        As[lc+0][lr] = a0.x; As[lc+1][lr] = a0.y; As[lc+2][lr] = a0.z; As[lc+3][lr] = a0.w;
        As[lc+0][lr+64] = a1.x; As[lc+1][lr+64] = a1.y; As[lc+2][lr+64] = a1.z; As[lc+3][lr+64] = a1.w;
        *(float4*)&Bs[bkr][bc] = bv;
        __syncthreads();
        #pragma unroll
        for (int kk = 0; kk < 16; kk++){
            float4 av = *(const float4*)&As[kk][ty*4];
            ulonglong2 b01 = *(const ulonglong2*)&Bs[kk][tx*8];
            ulonglong2 b23 = *(const ulonglong2*)&Bs[kk][tx*8 + 4];
            unsigned long long ad;
            ad = pack2(av.x, av.x);
            fma2(acc[0][0], ad, b01.x); fma2(acc[0][1], ad, b01.y);
            fma2(acc[0][2], ad, b23.x); fma2(acc[0][3], ad, b23.y);
            ad = pack2(av.y, av.y);
            fma2(acc[1][0], ad, b01.x); fma2(acc[1][1], ad, b01.y);
            fma2(acc[1][2], ad, b23.x); fma2(acc[1][3], ad, b23.y);
            ad = pack2(av.z, av.z);
            fma2(acc[2][0], ad, b01.x); fma2(acc[2][1], ad, b01.y);
            fma2(acc[2][2], ad, b23.x); fma2(acc[2][3], ad, b23.y);
            ad = pack2(av.w, av.w);
            fma2(acc[3][0], ad, b01.x); fma2(acc[3][1], ad, b01.y);
            fma2(acc[3][2], ad, b23.x); fma2(acc[3][3], ad, b23.y);
        }
    }

    #pragma unroll
    for (int r = 0; r < 4; r++){
        float cv[8];
        unpack2(acc[r][0], cv[0], cv[1]);
        unpack2(acc[r][1], cv[2], cv[3]);
        unpack2(acc[r][2], cv[4], cv[5]);
        unpack2(acc[r][3], cv[6], cv[7]);
        size_t row = (size_t)m0 + ty*4 + r;
        int nc = n0 + tx*8;
        #pragma unroll
        for (int c = 0; c < 8; c++){
            float v = cv[c] + bias[nc + c];
            if (GELU) v = 0.5f * v * (1.f + erff(v * 0.70710678118654752f));
            cv[c] = v;
        }
        float4* dst = (float4*)(Cm + row * (size_t)Ndim + nc);
        dst[0] = make_float4(cv[0], cv[1], cv[2], cv[3]);
        dst[1] = make_float4(cv[4], cv[5], cv[6], cv[7]);
    }
}

// ---------------- launch ----------------
extern "C" void kernel_launch(void* const* d_in, const int* in_sizes, int n_in,
                              void* d_out, int out_size){
    const float* X          = (const float*)d_in[0];
    const float* mask       = (const float*)d_in[1];
    const float* mask_atoms = (const float*)d_in[2];
    const float* means      = (const float*)d_in[3];
    const float* stds       = (const float*)d_in[4];
    const float* mul_w      = (const float*)d_in[5];
    const float* bias_w     = (const float*)d_in[6];
    const float* aa_pair    = (const float*)d_in[7];
    const float* relpos     = (const float*)d_in[8];
    const float* mask_emb   = (const float*)d_in[9];
    const float* W1         = (const float*)d_in[10];
    const float* b1         = (const float*)d_in[11];
    const float* W2         = (const float*)d_in[12];
    const float* b2         = (const float*)d_in[13];
    const int*   aa         = (const int*)d_in[14];
    const int*   residx     = (const int*)d_in[15];
    const int*   chains     = (const int*)d_in[16];
    float* out = (float*)d_out;

    float *pE, *pH, *pW1p, *pb1p, *pW2p;
    cudaGetSymbolAddress((void**)&pE,   g_E);
    cudaGetSymbolAddress((void**)&pH,   g_H);
    cudaGetSymbolAddress((void**)&pW1p, g_W1p);
    cudaGetSymbolAddress((void**)&pb1p, g_b1p);
    cudaGetSymbolAddress((void**)&pW2p, g_W2p);

    pad_weights_kernel<<<(cEPAD*cEPAD + 255)/256, 256>>>(W1, b1, W2);
    frames_kernel<<<(cB*cN + 127)/128, 128>>>(X);
    topk_kernel<<<cB*cN, 256>>>(X, mask);
    build_e_kernel<<<cM/4, 128>>>(X, mask_atoms, means, stds, mul_w, bias_w,
                                  aa_pair, relpos, mask_emb, aa, residx, chains);
    gemm_kernel<true ><<<dim3(cEPAD/64, cM/128), 256>>>(pE, pW1p, pb1p, pH, cEPAD, cEPAD);
    gemm_kernel<false><<<dim3(cEOUT/64, cM/128), 256>>>(pH, pW2p, b2, out, cEOUT, cEPAD);
}